// round 5
// baseline (speedup 1.0000x reference)
#include <cuda_runtime.h>
#include <cuda_bf16.h>
#include <cstddef>
#include <cstdint>

#define D 128
#define MAXG 100000

// scratch (device globals — no allocation allowed)
__device__ int   g_last[MAXG];
__device__ float g_A[D * D];
__device__ float g_bp[D];
__device__ float g_p[(size_t)MAXG * D];
__device__ float g_s[(size_t)MAXG * D];
// bf16 hi/lo splits of the two B matrices, stored as b_eff[n][k]
__device__ __nv_bfloat16 g_B1h[D * D], g_B1l[D * D];
__device__ __nv_bfloat16 g_B2h[D * D], g_B2l[D * D];

// ---------------------------------------------------------------- helpers
__device__ __forceinline__ float lo_of(float v) {
    return v - __bfloat162float(__float2bfloat16(v));
}
__device__ __forceinline__ uint32_t pack2(float a, float b) {
    __nv_bfloat162 h;
    h.x = __float2bfloat16(a);
    h.y = __float2bfloat16(b);
    return *(uint32_t*)&h;
}
__device__ __forceinline__ uint32_t smem_u32(const void* p) {
    uint32_t a;
    asm("{ .reg .u64 t; cvta.to.shared.u64 t, %1; cvt.u32.u64 %0, t; }"
        : "=r"(a) : "l"(p));
    return a;
}

#define MMA_BF16(cc, a0, a1, a2, a3, b0, b1)                                  \
    asm volatile(                                                             \
        "mma.sync.aligned.m16n8k16.row.col.f32.bf16.bf16.f32 "                \
        "{%0,%1,%2,%3}, {%4,%5,%6,%7}, {%8,%9}, {%0,%1,%2,%3};"               \
        : "+f"(cc[0]), "+f"(cc[1]), "+f"(cc[2]), "+f"(cc[3])                  \
        : "r"(a0), "r"(a1), "r"(a2), "r"(a3), "r"(b0), "r"(b1))

#define LDSM_X4(r, addr)                                                      \
    asm volatile("ldmatrix.sync.aligned.m8n8.x4.shared.b16 {%0,%1,%2,%3}, [%4];" \
                 : "=r"(r[0]), "=r"(r[1]), "=r"(r[2]), "=r"(r[3])             \
                 : "r"(addr))

// -------------------------------------------------------------------------
// 1) segment boundaries
// -------------------------------------------------------------------------
__global__ void bounds_kernel(const int* __restrict__ seg, int N) {
    int i = blockIdx.x * blockDim.x + threadIdx.x;
    if (i < N) {
        int sid = seg[i];
        if (i == N - 1 || seg[i + 1] != sid) g_last[sid] = i;
    }
}

// -------------------------------------------------------------------------
// 2) A = Wq^T @ Wk, b' = bq @ Wk
// -------------------------------------------------------------------------
__global__ void prep_kernel(const float* __restrict__ Wq, const float* __restrict__ bq,
                            const float* __restrict__ Wk) {
    int t = threadIdx.x;
    if (blockIdx.x < 64) {
        int idx = blockIdx.x * 256 + t;
        int i = idx >> 7, j = idx & 127;
        float sum = 0.f;
#pragma unroll 8
        for (int d = 0; d < D; d++) sum += Wq[d * D + i] * Wk[d * D + j];
        g_A[idx] = sum;
    } else if (t < D) {
        float sum = 0.f;
#pragma unroll 8
        for (int d = 0; d < D; d++) sum += bq[d] * Wk[d * D + t];
        g_bp[t] = sum;
    }
}

// -------------------------------------------------------------------------
// 2b) bf16 hi/lo split of both B matrices (b_eff[n][k] layout)
// -------------------------------------------------------------------------
__global__ void split_kernel(const float* __restrict__ Wk) {
    int idx = blockIdx.x * 256 + threadIdx.x;
    int n = idx >> 7, k = idx & 127;
    float v1 = g_A[k * D + n];
    g_B1h[idx] = __float2bfloat16(v1);
    g_B1l[idx] = __float2bfloat16(lo_of(v1));
    float v2 = Wk[idx];
    g_B2h[idx] = __float2bfloat16(v2);
    g_B2l[idx] = __float2bfloat16(lo_of(v2));
}

// -------------------------------------------------------------------------
// Tensor-core GEMM via mma.sync + ldmatrix:
//   C[M,128] = rows(Amat) @ b_eff^T + bias
//   3-term bf16 split (hi*hi + lo*hi + hi*lo), fp32 accumulate.
//   CTA tile 128x128, K=128 single shot in SMEM, 256 thr, warp tile 32x64.
// -------------------------------------------------------------------------
#define SROW 272                      // smem row stride in bytes (136 bf16)
#define OFF_AH 0
#define OFF_AL (128 * SROW)
#define OFF_BH (2 * 128 * SROW)
#define OFF_BL (3 * 128 * SROW)
#define SMEM_TOT (4 * 128 * SROW)     // 139264 B

__global__ void __launch_bounds__(256, 1)
mma_gemm_kernel(const float* __restrict__ Amat,
                const __nv_bfloat16* __restrict__ Bh,
                const __nv_bfloat16* __restrict__ Bl,
                const float* __restrict__ bias,
                const int* __restrict__ ridx,
                float* __restrict__ C, int M) {
    extern __shared__ char smem[];
    uint32_t sb = smem_u32(smem);
    int t = threadIdx.x, lane = t & 31, w = t >> 5;
    int mBase = blockIdx.x * 128;

    // ---- stage: A fp32 -> bf16 hi/lo, B hi/lo copy; 2 threads per row ----
    {
        int row = t >> 1;
        int kh = (t & 1) * 64;
        int m = mBase + row;
        if (m >= M) m = M - 1;
        int ar = ridx ? ridx[m] : m;
        const float* ap = Amat + (size_t)ar * D + kh;
        const __nv_bfloat16* bhp = Bh + row * D + kh;
        const __nv_bfloat16* blp = Bl + row * D + kh;
        char* sA_h = smem + OFF_AH + row * SROW + kh * 2;
        char* sA_l = smem + OFF_AL + row * SROW + kh * 2;
        char* sB_h = smem + OFF_BH + row * SROW + kh * 2;
        char* sB_l = smem + OFF_BL + row * SROW + kh * 2;
#pragma unroll
        for (int j = 0; j < 8; j++) {
            float4 v0 = *(const float4*)(ap + j * 8);
            float4 v1 = *(const float4*)(ap + j * 8 + 4);
            uint4 hi = {pack2(v0.x, v0.y), pack2(v0.z, v0.w),
                        pack2(v1.x, v1.y), pack2(v1.z, v1.w)};
            uint4 lo = {pack2(lo_of(v0.x), lo_of(v0.y)), pack2(lo_of(v0.z), lo_of(v0.w)),
                        pack2(lo_of(v1.x), lo_of(v1.y)), pack2(lo_of(v1.z), lo_of(v1.w))};
            *(uint4*)(sA_h + j * 16) = hi;
            *(uint4*)(sA_l + j * 16) = lo;
            *(uint4*)(sB_h + j * 16) = *(const uint4*)(bhp + j * 8);
            *(uint4*)(sB_l + j * 16) = *(const uint4*)(blp + j * 8);
        }
    }
    __syncthreads();

    // ---- compute: warp (w&3) -> m rows [32), (w>>2) -> n cols [64) ----
    int warpM = (w & 3) * 32;
    int warpN = (w >> 2) * 64;

    // ldmatrix per-thread base offsets (tile = lane/8 -> {r0k0,r8k0,r0k8,r8k8})
    int ldRow = ((lane >> 3) & 1) * 8 + (lane & 7);
    int ldK16 = (lane >> 4) * 16;  // bytes: +8 k elems for tiles 2,3
    uint32_t aOff = (uint32_t)((warpM + ldRow) * SROW + ldK16);
    uint32_t bOff = (uint32_t)((warpN + ldRow) * SROW + ldK16);

    float acc[2][8][4];
#pragma unroll
    for (int mb = 0; mb < 2; mb++)
#pragma unroll
        for (int nb = 0; nb < 8; nb++)
#pragma unroll
            for (int i = 0; i < 4; i++) acc[mb][nb][i] = 0.f;

#pragma unroll 1
    for (int ks = 0; ks < 8; ks++) {
        uint32_t kOffB = ks * 32;  // 16 k-elems * 2 bytes
        uint32_t ah[2][4], al[2][4];
#pragma unroll
        for (int mb = 0; mb < 2; mb++) {
            uint32_t base = aOff + mb * (16 * SROW) + kOffB;
            LDSM_X4(ah[mb], sb + OFF_AH + base);
            LDSM_X4(al[mb], sb + OFF_AL + base);
        }
#pragma unroll
        for (int nb2 = 0; nb2 < 4; nb2++) {
            uint32_t base = bOff + nb2 * (16 * SROW) + kOffB;
            uint32_t bh[4], bl[4];
            LDSM_X4(bh, sb + OFF_BH + base);
            LDSM_X4(bl, sb + OFF_BL + base);
#pragma unroll
            for (int mb = 0; mb < 2; mb++) {
                // even n-block: regs {0,2}; odd: {1,3}
                MMA_BF16(acc[mb][nb2 * 2],     ah[mb][0], ah[mb][1], ah[mb][2], ah[mb][3], bh[0], bh[2]);
                MMA_BF16(acc[mb][nb2 * 2],     al[mb][0], al[mb][1], al[mb][2], al[mb][3], bh[0], bh[2]);
                MMA_BF16(acc[mb][nb2 * 2],     ah[mb][0], ah[mb][1], ah[mb][2], ah[mb][3], bl[0], bl[2]);
                MMA_BF16(acc[mb][nb2 * 2 + 1], ah[mb][0], ah[mb][1], ah[mb][2], ah[mb][3], bh[1], bh[3]);
                MMA_BF16(acc[mb][nb2 * 2 + 1], al[mb][0], al[mb][1], al[mb][2], al[mb][3], bh[1], bh[3]);
                MMA_BF16(acc[mb][nb2 * 2 + 1], ah[mb][0], ah[mb][1], ah[mb][2], ah[mb][3], bl[1], bl[3]);
            }
        }
    }

    // ---- epilogue ----
    int g = lane >> 2, p = lane & 3;
#pragma unroll
    for (int mb = 0; mb < 2; mb++) {
        int r0 = mBase + warpM + mb * 16 + g;
        int r1 = r0 + 8;
#pragma unroll
        for (int nb = 0; nb < 8; nb++) {
            int col = warpN + nb * 8 + p * 2;
            float2 bv = *(const float2*)(bias + col);
            if (r0 < M) {
                float2 o = {acc[mb][nb][0] + bv.x, acc[mb][nb][1] + bv.y};
                *(float2*)(C + (size_t)r0 * D + col) = o;
            }
            if (r1 < M) {
                float2 o = {acc[mb][nb][2] + bv.x, acc[mb][nb][3] + bv.y};
                *(float2*)(C + (size_t)r1 * D + col) = o;
            }
        }
    }
}

// -------------------------------------------------------------------------
// 4) fused per-segment online softmax + weighted embedding sum (1 warp/group)
//    2 rows per iteration for MLP / shfl-chain overlap
// -------------------------------------------------------------------------
__global__ void seg_softmax_kernel(const float* __restrict__ emb, int G) {
    int w = (blockIdx.x * blockDim.x + threadIdx.x) >> 5;
    int lane = threadIdx.x & 31;
    if (w >= G) return;

    int start = (w == 0) ? 0 : (g_last[w - 1] + 1);
    int end   = g_last[w];

    float4 pv = *(const float4*)(g_p + (size_t)w * D + (lane << 2));
    const float4* erow = (const float4*)emb;

    float m = -1e30f, denom = 0.f;
    float4 acc = {0.f, 0.f, 0.f, 0.f};

    for (int r = start; r <= end; r += 2) {
        bool two = (r + 1 <= end);
        float4 c0 = erow[(size_t)r * 32 + lane];
        float4 c1 = two ? erow[(size_t)(r + 1) * 32 + lane] : c0;

        float q0 = c0.x * pv.x + c0.y * pv.y + c0.z * pv.z + c0.w * pv.w;
        float q1 = c1.x * pv.x + c1.y * pv.y + c1.z * pv.z + c1.w * pv.w;
#pragma unroll
        for (int off = 16; off > 0; off >>= 1) {
            q0 += __shfl_xor_sync(0xffffffffu, q0, off);
            q1 += __shfl_xor_sync(0xffffffffu, q1, off);
        }
        {
            float mnew = fmaxf(m, q0);
            float scale = __expf(m - mnew);
            float wgt = __expf(q0 - mnew);
            denom = denom * scale + wgt;
            acc.x = acc.x * scale + wgt * c0.x;
            acc.y = acc.y * scale + wgt * c0.y;
            acc.z = acc.z * scale + wgt * c0.z;
            acc.w = acc.w * scale + wgt * c0.w;
            m = mnew;
        }
        if (two) {
            float mnew = fmaxf(m, q1);
            float scale = __expf(m - mnew);
            float wgt = __expf(q1 - mnew);
            denom = denom * scale + wgt;
            acc.x = acc.x * scale + wgt * c1.x;
            acc.y = acc.y * scale + wgt * c1.y;
            acc.z = acc.z * scale + wgt * c1.z;
            acc.w = acc.w * scale + wgt * c1.w;
            m = mnew;
        }
    }

    float inv = 1.0f / denom;
    float4 o = {acc.x * inv, acc.y * inv, acc.z * inv, acc.w * inv};
    *(float4*)(g_s + (size_t)w * D + (lane << 2)) = o;
}

// -------------------------------------------------------------------------
extern "C" void kernel_launch(void* const* d_in, const int* in_sizes, int n_in,
                              void* d_out, int out_size) {
    const float* emb = (const float*)d_in[0];
    const int*   seg = (const int*)d_in[1];
    const float* Wq  = (const float*)d_in[2];
    const float* bq  = (const float*)d_in[3];
    const float* Wk  = (const float*)d_in[4];
    const float* bk  = (const float*)d_in[5];
    float* out = (float*)d_out;

    int N = in_sizes[0] / D;
    int G = out_size / D;

    static bool attr_done = false;
    if (!attr_done) {
        cudaFuncSetAttribute(mma_gemm_kernel,
                             cudaFuncAttributeMaxDynamicSharedMemorySize, SMEM_TOT);
        attr_done = true;
    }

    void *pLast, *pBp, *pP, *pS, *pB1h, *pB1l, *pB2h, *pB2l;
    cudaGetSymbolAddress(&pLast, g_last);
    cudaGetSymbolAddress(&pBp, g_bp);
    cudaGetSymbolAddress(&pP, g_p);
    cudaGetSymbolAddress(&pS, g_s);
    cudaGetSymbolAddress(&pB1h, g_B1h);
    cudaGetSymbolAddress(&pB1l, g_B1l);
    cudaGetSymbolAddress(&pB2h, g_B2h);
    cudaGetSymbolAddress(&pB2l, g_B2l);

    bounds_kernel<<<(N + 255) / 256, 256>>>(seg, N);
    prep_kernel<<<65, 256>>>(Wq, bq, Wk);
    split_kernel<<<64, 256>>>(Wk);

    int nblk = (G + 127) / 128;

    // p[G,128] = emb[last] @ Aqk + b'
    mma_gemm_kernel<<<nblk, 256, SMEM_TOT>>>(
        emb, (const __nv_bfloat16*)pB1h, (const __nv_bfloat16*)pB1l,
        (const float*)pBp, (const int*)pLast, (float*)pP, G);

    // fused segment softmax -> s[G,128]
    seg_softmax_kernel<<<(G + 7) / 8, 256>>>(emb, G);

    // out = s @ Wk^T + bk
    mma_gemm_kernel<<<nblk, 256, SMEM_TOT>>>(
        (const float*)pS, (const __nv_bfloat16*)pB2h, (const __nv_bfloat16*)pB2l,
        bk, nullptr, out, G);
}

// round 6
// speedup vs baseline: 1.1895x; 1.1895x over previous
#include <cuda_runtime.h>
#include <cuda_bf16.h>
#include <cstddef>
#include <cstdint>

#define D 128
#define MAXG 100000

// scratch (device globals — no allocation allowed)
__device__ int   g_last[MAXG];
__device__ float g_A[D * D];
__device__ float g_bp[D];
__device__ float g_p[(size_t)MAXG * D];
__device__ float g_s[(size_t)MAXG * D];
// bf16 hi/lo splits of the two B matrices, stored as b_eff[n][k]
__device__ __nv_bfloat16 g_B1h[D * D], g_B1l[D * D];
__device__ __nv_bfloat16 g_B2h[D * D], g_B2l[D * D];

// ---------------------------------------------------------------- helpers
__device__ __forceinline__ float lo_of(float v) {
    return v - __bfloat162float(__float2bfloat16(v));
}
__device__ __forceinline__ uint32_t pack2(float a, float b) {
    __nv_bfloat162 h;
    h.x = __float2bfloat16(a);
    h.y = __float2bfloat16(b);
    return *(uint32_t*)&h;
}
__device__ __forceinline__ uint32_t smem_u32(const void* p) {
    uint32_t a;
    asm("{ .reg .u64 t; cvta.to.shared.u64 t, %1; cvt.u32.u64 %0, t; }"
        : "=r"(a) : "l"(p));
    return a;
}

#define MMA_BF16(cc, a0, a1, a2, a3, b0, b1)                                  \
    asm volatile(                                                             \
        "mma.sync.aligned.m16n8k16.row.col.f32.bf16.bf16.f32 "                \
        "{%0,%1,%2,%3}, {%4,%5,%6,%7}, {%8,%9}, {%0,%1,%2,%3};"               \
        : "+f"(cc[0]), "+f"(cc[1]), "+f"(cc[2]), "+f"(cc[3])                  \
        : "r"(a0), "r"(a1), "r"(a2), "r"(a3), "r"(b0), "r"(b1))

#define LDSM_X4(r, addr)                                                      \
    asm volatile("ldmatrix.sync.aligned.m8n8.x4.shared.b16 {%0,%1,%2,%3}, [%4];" \
                 : "=r"(r[0]), "=r"(r[1]), "=r"(r[2]), "=r"(r[3])             \
                 : "r"(addr))

// -------------------------------------------------------------------------
// 1) segment boundaries
// -------------------------------------------------------------------------
__global__ void bounds_kernel(const int* __restrict__ seg, int N) {
    int i = blockIdx.x * blockDim.x + threadIdx.x;
    if (i < N) {
        int sid = seg[i];
        if (i == N - 1 || seg[i + 1] != sid) g_last[sid] = i;
    }
}

// -------------------------------------------------------------------------
// 2) A = Wq^T @ Wk, b' = bq @ Wk
// -------------------------------------------------------------------------
__global__ void prep_kernel(const float* __restrict__ Wq, const float* __restrict__ bq,
                            const float* __restrict__ Wk) {
    int t = threadIdx.x;
    if (blockIdx.x < 64) {
        int idx = blockIdx.x * 256 + t;
        int i = idx >> 7, j = idx & 127;
        float sum = 0.f;
#pragma unroll 8
        for (int d = 0; d < D; d++) sum += Wq[d * D + i] * Wk[d * D + j];
        g_A[idx] = sum;
    } else if (t < D) {
        float sum = 0.f;
#pragma unroll 8
        for (int d = 0; d < D; d++) sum += bq[d] * Wk[d * D + t];
        g_bp[t] = sum;
    }
}

// -------------------------------------------------------------------------
// 2b) bf16 hi/lo split of both B matrices (b_eff[n][k] layout)
// -------------------------------------------------------------------------
__global__ void split_kernel(const float* __restrict__ Wk) {
    int idx = blockIdx.x * 256 + threadIdx.x;
    int n = idx >> 7, k = idx & 127;
    float v1 = g_A[k * D + n];
    g_B1h[idx] = __float2bfloat16(v1);
    g_B1l[idx] = __float2bfloat16(lo_of(v1));
    float v2 = Wk[idx];
    g_B2h[idx] = __float2bfloat16(v2);
    g_B2l[idx] = __float2bfloat16(lo_of(v2));
}

// -------------------------------------------------------------------------
// Tensor-core GEMM via mma.sync + ldmatrix:
//   C[M,128] = rows(Amat) @ b_eff^T + bias
//   3-term bf16 split (hi*hi + lo*hi + hi*lo), fp32 accumulate.
//   CTA tile 128x128, K chunked at 64 (2 chunks), 256 thr, warp tile 32x64.
//   SMEM 73.7 KB -> 2 CTAs/SM.
// -------------------------------------------------------------------------
#define KC   64                       // k-chunk (elements)
#define SROW 144                      // smem row stride in bytes (64*2 + 16)
#define OFF_AH 0
#define OFF_AL (128 * SROW)
#define OFF_BH (2 * 128 * SROW)
#define OFF_BL (3 * 128 * SROW)
#define SMEM_TOT (4 * 128 * SROW)     // 73728 B

__global__ void __launch_bounds__(256, 2)
mma_gemm_kernel(const float* __restrict__ Amat,
                const __nv_bfloat16* __restrict__ Bh,
                const __nv_bfloat16* __restrict__ Bl,
                const float* __restrict__ bias,
                const int* __restrict__ ridx,
                float* __restrict__ C, int M) {
    extern __shared__ char smem[];
    uint32_t sb = smem_u32(smem);
    int t = threadIdx.x, lane = t & 31, w = t >> 5;
    int mBase = blockIdx.x * 128;

    // staging mapping: 2 threads per row, 32 k-elements each
    int row = t >> 1;
    int kh = (t & 1) * 32;
    int m = mBase + row;
    if (m >= M) m = M - 1;
    int ar = ridx ? ridx[m] : m;
    const float* ap = Amat + (size_t)ar * D + kh;
    const __nv_bfloat16* bhp = Bh + row * D + kh;
    const __nv_bfloat16* blp = Bl + row * D + kh;
    char* sA_h = smem + OFF_AH + row * SROW + kh * 2;
    char* sA_l = smem + OFF_AL + row * SROW + kh * 2;
    char* sB_h = smem + OFF_BH + row * SROW + kh * 2;
    char* sB_l = smem + OFF_BL + row * SROW + kh * 2;

    // compute mapping: warp (w&3) -> m rows [32), (w>>2) -> n cols [64)
    int warpM = (w & 3) * 32;
    int warpN = (w >> 2) * 64;
    int ldRow = ((lane >> 3) & 1) * 8 + (lane & 7);
    int ldK16 = (lane >> 4) * 16;
    uint32_t aOff = (uint32_t)((warpM + ldRow) * SROW + ldK16);
    uint32_t bOff = (uint32_t)((warpN + ldRow) * SROW + ldK16);

    float acc[2][8][4];
#pragma unroll
    for (int mb = 0; mb < 2; mb++)
#pragma unroll
        for (int nb = 0; nb < 8; nb++)
#pragma unroll
            for (int i = 0; i < 4; i++) acc[mb][nb][i] = 0.f;

#pragma unroll 1
    for (int kc = 0; kc < 2; kc++) {
        if (kc) __syncthreads();
        // ---- stage chunk kc ----
        {
            const float* a = ap + kc * KC;
#pragma unroll
            for (int j = 0; j < 4; j++) {
                float4 v0 = *(const float4*)(a + j * 8);
                float4 v1 = *(const float4*)(a + j * 8 + 4);
                uint4 hi = {pack2(v0.x, v0.y), pack2(v0.z, v0.w),
                            pack2(v1.x, v1.y), pack2(v1.z, v1.w)};
                uint4 lo = {pack2(lo_of(v0.x), lo_of(v0.y)), pack2(lo_of(v0.z), lo_of(v0.w)),
                            pack2(lo_of(v1.x), lo_of(v1.y)), pack2(lo_of(v1.z), lo_of(v1.w))};
                *(uint4*)(sA_h + j * 16) = hi;
                *(uint4*)(sA_l + j * 16) = lo;
                *(uint4*)(sB_h + j * 16) = *(const uint4*)(bhp + kc * KC + j * 8);
                *(uint4*)(sB_l + j * 16) = *(const uint4*)(blp + kc * KC + j * 8);
            }
        }
        __syncthreads();

        // ---- compute 4 k-steps of this chunk ----
#pragma unroll
        for (int ks = 0; ks < 4; ks++) {
            uint32_t kOffB = ks * 32;
            uint32_t ah[2][4], al[2][4];
#pragma unroll
            for (int mb = 0; mb < 2; mb++) {
                uint32_t base = aOff + mb * (16 * SROW) + kOffB;
                LDSM_X4(ah[mb], sb + OFF_AH + base);
                LDSM_X4(al[mb], sb + OFF_AL + base);
            }
#pragma unroll
            for (int nb2 = 0; nb2 < 4; nb2++) {
                uint32_t base = bOff + nb2 * (16 * SROW) + kOffB;
                uint32_t bh[4], bl[4];
                LDSM_X4(bh, sb + OFF_BH + base);
                LDSM_X4(bl, sb + OFF_BL + base);
#pragma unroll
                for (int mb = 0; mb < 2; mb++) {
                    MMA_BF16(acc[mb][nb2 * 2],     ah[mb][0], ah[mb][1], ah[mb][2], ah[mb][3], bh[0], bh[2]);
                    MMA_BF16(acc[mb][nb2 * 2],     al[mb][0], al[mb][1], al[mb][2], al[mb][3], bh[0], bh[2]);
                    MMA_BF16(acc[mb][nb2 * 2],     ah[mb][0], ah[mb][1], ah[mb][2], ah[mb][3], bl[0], bl[2]);
                    MMA_BF16(acc[mb][nb2 * 2 + 1], ah[mb][0], ah[mb][1], ah[mb][2], ah[mb][3], bh[1], bh[3]);
                    MMA_BF16(acc[mb][nb2 * 2 + 1], al[mb][0], al[mb][1], al[mb][2], al[mb][3], bh[1], bh[3]);
                    MMA_BF16(acc[mb][nb2 * 2 + 1], ah[mb][0], ah[mb][1], ah[mb][2], ah[mb][3], bl[1], bl[3]);
                }
            }
        }
    }

    // ---- epilogue ----
    int g = lane >> 2, p = lane & 3;
#pragma unroll
    for (int mb = 0; mb < 2; mb++) {
        int r0 = mBase + warpM + mb * 16 + g;
        int r1 = r0 + 8;
#pragma unroll
        for (int nb = 0; nb < 8; nb++) {
            int col = warpN + nb * 8 + p * 2;
            float2 bv = *(const float2*)(bias + col);
            if (r0 < M) {
                float2 o = {acc[mb][nb][0] + bv.x, acc[mb][nb][1] + bv.y};
                *(float2*)(C + (size_t)r0 * D + col) = o;
            }
            if (r1 < M) {
                float2 o = {acc[mb][nb][2] + bv.x, acc[mb][nb][3] + bv.y};
                *(float2*)(C + (size_t)r1 * D + col) = o;
            }
        }
    }
}

// -------------------------------------------------------------------------
// 4) fused per-segment online softmax + weighted embedding sum (1 warp/group)
//    4 rows per iteration, batched online update
// -------------------------------------------------------------------------
__global__ void seg_softmax_kernel(const float* __restrict__ emb, int G) {
    int w = (blockIdx.x * blockDim.x + threadIdx.x) >> 5;
    int lane = threadIdx.x & 31;
    if (w >= G) return;

    int start = (w == 0) ? 0 : (g_last[w - 1] + 1);
    int end   = g_last[w];

    float4 pv = *(const float4*)(g_p + (size_t)w * D + (lane << 2));
    const float4* erow = (const float4*)emb;

    float m = -1e30f, denom = 0.f;
    float4 acc = {0.f, 0.f, 0.f, 0.f};

    for (int r = start; r <= end; r += 4) {
        int r1 = (r + 1 <= end) ? r + 1 : end;
        int r2 = (r + 2 <= end) ? r + 2 : end;
        int r3 = (r + 3 <= end) ? r + 3 : end;
        float4 c0 = erow[(size_t)r  * 32 + lane];
        float4 c1 = erow[(size_t)r1 * 32 + lane];
        float4 c2 = erow[(size_t)r2 * 32 + lane];
        float4 c3 = erow[(size_t)r3 * 32 + lane];

        float q0 = c0.x * pv.x + c0.y * pv.y + c0.z * pv.z + c0.w * pv.w;
        float q1 = c1.x * pv.x + c1.y * pv.y + c1.z * pv.z + c1.w * pv.w;
        float q2 = c2.x * pv.x + c2.y * pv.y + c2.z * pv.z + c2.w * pv.w;
        float q3 = c3.x * pv.x + c3.y * pv.y + c3.z * pv.z + c3.w * pv.w;
#pragma unroll
        for (int off = 16; off > 0; off >>= 1) {
            q0 += __shfl_xor_sync(0xffffffffu, q0, off);
            q1 += __shfl_xor_sync(0xffffffffu, q1, off);
            q2 += __shfl_xor_sync(0xffffffffu, q2, off);
            q3 += __shfl_xor_sync(0xffffffffu, q3, off);
        }
        // mask duplicated (clamped) rows out
        if (r + 1 > end) q1 = -1e30f;
        if (r + 2 > end) q2 = -1e30f;
        if (r + 3 > end) q3 = -1e30f;

        float mnew = fmaxf(fmaxf(fmaxf(m, q0), fmaxf(q1, q2)), q3);
        float scale = __expf(m - mnew);
        float w0 = __expf(q0 - mnew);
        float w1 = __expf(q1 - mnew);
        float w2 = __expf(q2 - mnew);
        float w3 = __expf(q3 - mnew);
        denom = denom * scale + ((w0 + w1) + (w2 + w3));
        acc.x = acc.x * scale + w0 * c0.x + w1 * c1.x + w2 * c2.x + w3 * c3.x;
        acc.y = acc.y * scale + w0 * c0.y + w1 * c1.y + w2 * c2.y + w3 * c3.y;
        acc.z = acc.z * scale + w0 * c0.z + w1 * c1.z + w2 * c2.z + w3 * c3.z;
        acc.w = acc.w * scale + w0 * c0.w + w1 * c1.w + w2 * c2.w + w3 * c3.w;
        m = mnew;
    }

    float inv = 1.0f / denom;
    float4 o = {acc.x * inv, acc.y * inv, acc.z * inv, acc.w * inv};
    *(float4*)(g_s + (size_t)w * D + (lane << 2)) = o;
}

// -------------------------------------------------------------------------
extern "C" void kernel_launch(void* const* d_in, const int* in_sizes, int n_in,
                              void* d_out, int out_size) {
    const float* emb = (const float*)d_in[0];
    const int*   seg = (const int*)d_in[1];
    const float* Wq  = (const float*)d_in[2];
    const float* bq  = (const float*)d_in[3];
    const float* Wk  = (const float*)d_in[4];
    const float* bk  = (const float*)d_in[5];
    float* out = (float*)d_out;

    int N = in_sizes[0] / D;
    int G = out_size / D;

    static bool attr_done = false;
    if (!attr_done) {
        cudaFuncSetAttribute(mma_gemm_kernel,
                             cudaFuncAttributeMaxDynamicSharedMemorySize, SMEM_TOT);
        attr_done = true;
    }

    void *pLast, *pBp, *pP, *pS, *pB1h, *pB1l, *pB2h, *pB2l;
    cudaGetSymbolAddress(&pLast, g_last);
    cudaGetSymbolAddress(&pBp, g_bp);
    cudaGetSymbolAddress(&pP, g_p);
    cudaGetSymbolAddress(&pS, g_s);
    cudaGetSymbolAddress(&pB1h, g_B1h);
    cudaGetSymbolAddress(&pB1l, g_B1l);
    cudaGetSymbolAddress(&pB2h, g_B2h);
    cudaGetSymbolAddress(&pB2l, g_B2l);

    bounds_kernel<<<(N + 255) / 256, 256>>>(seg, N);
    prep_kernel<<<65, 256>>>(Wq, bq, Wk);
    split_kernel<<<64, 256>>>(Wk);

    int nblk = (G + 127) / 128;

    // p[G,128] = emb[last] @ Aqk + b'
    mma_gemm_kernel<<<nblk, 256, SMEM_TOT>>>(
        emb, (const __nv_bfloat16*)pB1h, (const __nv_bfloat16*)pB1l,
        (const float*)pBp, (const int*)pLast, (float*)pP, G);

    // fused segment softmax -> s[G,128]
    seg_softmax_kernel<<<(G + 7) / 8, 256>>>(emb, G);

    // out = s @ Wk^T + bk
    mma_gemm_kernel<<<nblk, 256, SMEM_TOT>>>(
        (const float*)pS, (const __nv_bfloat16*)pB2h, (const __nv_bfloat16*)pB2l,
        bk, nullptr, out, G);
}